// round 1
// baseline (speedup 1.0000x reference)
#include <cuda_runtime.h>
#include <cstdint>

// Problem constants (fixed by the dataset)
#define MAXN 50000
#define FIN  48
#define HID  32
#define NCLS 10
#define KS   4
#define J1   160   // 128 xw1 outputs + 32 root outputs
#define NB   8     // node tile

// ---------------- scratch (device globals; no allocations allowed) -------------
__device__ float g_xw1 [MAXN * KS * HID];   // [N][4][32]
__device__ float g_rb1 [MAXN * HID];        // x@root1 + bias1
__device__ float g_agg1[MAXN * HID];
__device__ float g_deg [MAXN];
__device__ float g_xw2 [MAXN * KS * NCLS];  // [N][4][10]
__device__ float g_rb2 [MAXN * NCLS];       // h@root2 + bias2
__device__ float g_agg2[MAXN * NCLS];
__device__ int   g_is64;

// ---------------- helpers ------------------------------------------------------
__device__ __forceinline__ void red_add_v4(float* addr, float4 v) {
    asm volatile("red.global.add.v4.f32 [%0], {%1,%2,%3,%4};"
                 :: "l"(addr), "f"(v.x), "f"(v.y), "f"(v.z), "f"(v.w) : "memory");
}
__device__ __forceinline__ void red_add_v2(float* addr, float2 v) {
    asm volatile("red.global.add.v2.f32 [%0], {%1,%2};"
                 :: "l"(addr), "f"(v.x), "f"(v.y) : "memory");
}

// detect whether edge_index is int64 (hi words all zero) or int32
__global__ void k_detect(const void* __restrict__ ei) {
    int i = threadIdx.x;                       // 32 threads
    int hi = ((const int*)ei)[2 * i + 1];
    unsigned b = __ballot_sync(0xffffffffu, hi != 0);
    if (i == 0) g_is64 = (b == 0) ? 1 : 0;
}

// zero agg1, deg, agg2
__global__ void k_zero(int N) {
    int tot = N * HID + N + N * NCLS;
    for (int i = blockIdx.x * blockDim.x + threadIdx.x; i < tot; i += gridDim.x * blockDim.x) {
        if (i < N * HID)            g_agg1[i] = 0.f;
        else if (i < N * HID + N)   g_deg[i - N * HID] = 0.f;
        else                        g_agg2[i - N * HID - N] = 0.f;
    }
}

// ---------------- layer-1 node precompute: xw1 = x@W1 (per k), rb1 = x@root1+b1 --
__global__ void __launch_bounds__(J1) k_xw1(const float* __restrict__ x,
                                            const float* __restrict__ W1,
                                            const float* __restrict__ root1,
                                            const float* __restrict__ bias1, int N) {
    const int j = threadIdx.x;                 // 0..159, fixed output column
    float wcol[FIN];
    float binit = 0.f;
    if (j < 128) {
        int k = j >> 5, o = j & 31;
        #pragma unroll
        for (int f = 0; f < FIN; f++) wcol[f] = W1[(k * FIN + f) * HID + o];
    } else {
        int o = j - 128;
        #pragma unroll
        for (int f = 0; f < FIN; f++) wcol[f] = root1[f * HID + o];
        binit = bias1[o];
    }
    __shared__ float xs[FIN * NB];             // transposed: [f][nn]
    int ntiles = (N + NB - 1) / NB;
    for (int tile = blockIdx.x; tile < ntiles; tile += gridDim.x) {
        int n0 = tile * NB;
        __syncthreads();
        for (int idx = j; idx < FIN * NB; idx += J1) {
            int nn = idx / FIN, f = idx % FIN;
            int n = n0 + nn;
            xs[f * NB + nn] = (n < N) ? x[n * FIN + f] : 0.f;
        }
        __syncthreads();
        float acc[NB];
        #pragma unroll
        for (int nn = 0; nn < NB; nn++) acc[nn] = binit;
        #pragma unroll
        for (int f = 0; f < FIN; f++) {
            float4 xa = *(const float4*)&xs[f * NB];
            float4 xb = *(const float4*)&xs[f * NB + 4];
            float w = wcol[f];
            acc[0] += xa.x * w; acc[1] += xa.y * w; acc[2] += xa.z * w; acc[3] += xa.w * w;
            acc[4] += xb.x * w; acc[5] += xb.y * w; acc[6] += xb.z * w; acc[7] += xb.w * w;
        }
        #pragma unroll
        for (int nn = 0; nn < NB; nn++) {
            int n = n0 + nn;
            if (n < N) {
                if (j < 128) g_xw1[n * 128 + j]       = acc[nn];
                else         g_rb1[n * HID + (j - 128)] = acc[nn];
            }
        }
    }
}

// ---------------- layer-1 edge scatter: warp = 4 edges x 8 lanes (float4) --------
__global__ void __launch_bounds__(256) k_edge1(const void* __restrict__ ei,
                                               const float* __restrict__ ea, int E) {
    int t = blockIdx.x * blockDim.x + threadIdx.x;
    int lane = t & 31;
    int g = lane >> 3;          // which edge in group of 4
    int f4 = lane & 7;          // float4 slot (8 x float4 = 32 feats)
    long long e = ((long long)(t >> 5)) * 4 + g;
    if (e >= E) return;
    long long src, dst;
    if (g_is64) {
        src = ((const long long*)ei)[e];
        dst = ((const long long*)ei)[(long long)E + e];
    } else {
        src = ((const int*)ei)[e];
        dst = ((const int*)ei)[(long long)E + e];
    }
    float u = ea[e];
    float vv = u * (float)(KS - 1);
    float vf = floorf(vv);
    float frac = vv - vf;
    int k0 = min(max((int)vf, 0), KS - 1);
    int k1 = min(k0 + 1, KS - 1);
    const float4* xw = (const float4*)g_xw1;   // 32 float4 per node
    float4 a = xw[src * 32 + k0 * 8 + f4];
    float4 b = xw[src * 32 + k1 * 8 + f4];
    float w0 = 1.0f - frac;
    float4 m = make_float4(w0 * a.x + frac * b.x, w0 * a.y + frac * b.y,
                           w0 * a.z + frac * b.z, w0 * a.w + frac * b.w);
    red_add_v4(&g_agg1[dst * HID + f4 * 4], m);
    if (f4 == 0) atomicAdd(&g_deg[dst], 1.0f);
}

// ---------------- layer-2 node prep: h = elu(agg1/deg + rb1); xw2, rb2 ----------
__global__ void __launch_bounds__(64) k_prep2(const float* __restrict__ W2,
                                              const float* __restrict__ root2,
                                              const float* __restrict__ bias2, int N) {
    const int j = threadIdx.x;                 // 0..63; active j<50
    bool active = (j < 50);
    float wcol[HID];
    float binit = 0.f;
    if (j < 40) {
        int k = j / NCLS, c = j % NCLS;
        #pragma unroll
        for (int o = 0; o < HID; o++) wcol[o] = W2[(k * HID + o) * NCLS + c];
    } else if (j < 50) {
        int c = j - 40;
        #pragma unroll
        for (int o = 0; o < HID; o++) wcol[o] = root2[o * NCLS + c];
        binit = bias2[c];
    }
    __shared__ float hs[HID * NB];             // transposed: [o][nn]
    int ntiles = (N + NB - 1) / NB;
    for (int tile = blockIdx.x; tile < ntiles; tile += gridDim.x) {
        int n0 = tile * NB;
        __syncthreads();
        for (int idx = j; idx < HID * NB; idx += 64) {
            int nn = idx / HID, o = idx % HID;
            int n = n0 + nn;
            float h = 0.f;
            if (n < N) {
                float d = fmaxf(g_deg[n], 1.0f);
                float v = g_agg1[n * HID + o] / d + g_rb1[n * HID + o];
                h = (v > 0.f) ? v : expm1f(v);
            }
            hs[o * NB + nn] = h;
        }
        __syncthreads();
        if (active) {
            float acc[NB];
            #pragma unroll
            for (int nn = 0; nn < NB; nn++) acc[nn] = binit;
            #pragma unroll
            for (int o = 0; o < HID; o++) {
                float4 ha = *(const float4*)&hs[o * NB];
                float4 hb = *(const float4*)&hs[o * NB + 4];
                float w = wcol[o];
                acc[0] += ha.x * w; acc[1] += ha.y * w; acc[2] += ha.z * w; acc[3] += ha.w * w;
                acc[4] += hb.x * w; acc[5] += hb.y * w; acc[6] += hb.z * w; acc[7] += hb.w * w;
            }
            #pragma unroll
            for (int nn = 0; nn < NB; nn++) {
                int n = n0 + nn;
                if (n < N) {
                    if (j < 40) g_xw2[n * 40 + j]          = acc[nn];
                    else        g_rb2[n * NCLS + (j - 40)] = acc[nn];
                }
            }
        }
    }
}

// ---------------- layer-2 edge scatter: warp = 4 edges x 8 lanes (5 x float2) ----
__global__ void __launch_bounds__(256) k_edge2(const void* __restrict__ ei,
                                               const float* __restrict__ ea, int E) {
    int t = blockIdx.x * blockDim.x + threadIdx.x;
    int lane = t & 31;
    int g = lane >> 3;
    int j = lane & 7;           // float2 slot; only j<5 active
    long long e = ((long long)(t >> 5)) * 4 + g;
    if (e >= E || j >= 5) return;
    long long src, dst;
    if (g_is64) {
        src = ((const long long*)ei)[e];
        dst = ((const long long*)ei)[(long long)E + e];
    } else {
        src = ((const int*)ei)[e];
        dst = ((const int*)ei)[(long long)E + e];
    }
    float u = ea[e];
    float vv = u * (float)(KS - 1);
    float vf = floorf(vv);
    float frac = vv - vf;
    int k0 = min(max((int)vf, 0), KS - 1);
    int k1 = min(k0 + 1, KS - 1);
    const float2* xw = (const float2*)g_xw2;   // 20 float2 per node
    float2 a = xw[src * 20 + k0 * 5 + j];
    float2 b = xw[src * 20 + k1 * 5 + j];
    float w0 = 1.0f - frac;
    float2 m = make_float2(w0 * a.x + frac * b.x, w0 * a.y + frac * b.y);
    red_add_v2(&g_agg2[dst * NCLS + j * 2], m);
}

// ---------------- final: mean + root + bias + log_softmax -----------------------
__global__ void k_out(float* __restrict__ out, int N) {
    int n = blockIdx.x * blockDim.x + threadIdx.x;
    if (n >= N) return;
    float inv = 1.0f / fmaxf(g_deg[n], 1.0f);
    float v[NCLS];
    float mx = -1e30f;
    #pragma unroll
    for (int c = 0; c < NCLS; c++) {
        v[c] = g_agg2[n * NCLS + c] * inv + g_rb2[n * NCLS + c];
        mx = fmaxf(mx, v[c]);
    }
    float s = 0.f;
    #pragma unroll
    for (int c = 0; c < NCLS; c++) s += expf(v[c] - mx);
    float ls = logf(s) + mx;
    #pragma unroll
    for (int c = 0; c < NCLS; c++) out[n * NCLS + c] = v[c] - ls;
}

// ---------------- launch --------------------------------------------------------
extern "C" void kernel_launch(void* const* d_in, const int* in_sizes, int n_in,
                              void* d_out, int out_size) {
    const float* x     = (const float*)d_in[0];
    const void*  ei    =               d_in[1];
    const float* ea    = (const float*)d_in[2];
    const float* W1    = (const float*)d_in[3];
    const float* root1 = (const float*)d_in[4];
    const float* bias1 = (const float*)d_in[5];
    const float* W2    = (const float*)d_in[6];
    const float* root2 = (const float*)d_in[7];
    const float* bias2 = (const float*)d_in[8];
    float* out = (float*)d_out;

    int N = in_sizes[0] / FIN;     // 50000
    int E = in_sizes[2];           // 1600000 (edge_attr element count)

    int zgrid = (N * (HID + 1 + NCLS) + 255) / 256;
    k_zero<<<zgrid, 256>>>(N);
    k_detect<<<1, 32>>>(ei);
    k_xw1<<<592, J1>>>(x, W1, root1, bias1, N);
    int egrid = (E + 31) / 32;     // 32 edges per 256-thread block
    k_edge1<<<egrid, 256>>>(ei, ea, E);
    k_prep2<<<1184, 64>>>(W2, root2, bias2, N);
    k_edge2<<<egrid, 256>>>(ei, ea, E);
    k_out<<<(N + 255) / 256, 256>>>(out, N);
}